// round 7
// baseline (speedup 1.0000x reference)
#include <cuda_runtime.h>
#include <cuda_bf16.h>
#include <stdint.h>
#include <math.h>

#define Bb    2
#define Nn    1024
#define DIMM  1024
#define HEADS 16
#define HD    64
#define Mtot  (Bb * Nn)      // 2048
#define E3    (3 * DIMM)     // 3072

// ---------------- bf16 hi/lo split scratch -----------------------------------
__device__ __nv_bfloat16 g_Xr_h[Mtot * DIMM], g_Xr_l[Mtot * DIMM];
__device__ __nv_bfloat16 g_Xi_h[Mtot * DIMM], g_Xi_l[Mtot * DIMM];
__device__ __nv_bfloat16 g_Xs_h[Mtot * DIMM], g_Xs_l[Mtot * DIMM];
__device__ __nv_bfloat16 g_Wqr_h[E3 * DIMM],  g_Wqr_l[E3 * DIMM];
__device__ __nv_bfloat16 g_Wqi_h[E3 * DIMM],  g_Wqi_l[E3 * DIMM];
__device__ __nv_bfloat16 g_Wqs_h[E3 * DIMM],  g_Wqs_l[E3 * DIMM];
__device__ __nv_bfloat16 g_Wor_h[DIMM * DIMM], g_Wor_l[DIMM * DIMM];
__device__ __nv_bfloat16 g_Woi_h[DIMM * DIMM], g_Woi_l[DIMM * DIMM];
__device__ __nv_bfloat16 g_Wos_h[DIMM * DIMM], g_Wos_l[DIMM * DIMM];
__device__ __nv_bfloat16 g_Ar_h[Mtot * DIMM], g_Ar_l[Mtot * DIMM];
__device__ __nv_bfloat16 g_Ai_h[Mtot * DIMM], g_Ai_l[Mtot * DIMM];
__device__ __nv_bfloat16 g_As_h[Mtot * DIMM], g_As_l[Mtot * DIMM];

// Q/K/V bf16 hi/lo, layout [b*H + h][n][d]
#define QKV_SZ (Bb * HEADS * Nn * HD)
__device__ __nv_bfloat16 g_Qrh[QKV_SZ], g_Qrl[QKV_SZ], g_Qih[QKV_SZ], g_Qil[QKV_SZ];
__device__ __nv_bfloat16 g_Krh[QKV_SZ], g_Krl[QKV_SZ], g_Kih[QKV_SZ], g_Kil[QKV_SZ];
__device__ __nv_bfloat16 g_Vrh[QKV_SZ], g_Vrl[QKV_SZ], g_Vih[QKV_SZ], g_Vil[QKV_SZ];

// ---------------- helpers ----------------------------------------------------
__device__ __forceinline__ uint32_t smem_u32(const void* p) {
    uint32_t a;
    asm("{ .reg .u64 t; cvta.to.shared.u64 t, %1; cvt.u32.u64 %0, t; }"
        : "=r"(a) : "l"(p));
    return a;
}

#define CP16(dst, src) \
    asm volatile("cp.async.cg.shared.global [%0], [%1], 16;" \
                 :: "r"((uint32_t)(dst)), "l"(src) : "memory")
#define CP_COMMIT() asm volatile("cp.async.commit_group;" ::: "memory")
#define CP_WAIT(n)  asm volatile("cp.async.wait_group %0;" :: "n"(n) : "memory")

__device__ __forceinline__ void ldm_x4(uint32_t* r, uint32_t addr) {
    asm volatile("ldmatrix.sync.aligned.m8n8.x4.shared.b16 {%0,%1,%2,%3}, [%4];"
        : "=r"(r[0]), "=r"(r[1]), "=r"(r[2]), "=r"(r[3]) : "r"(addr));
}

__device__ __forceinline__ void ldm_x4_t(uint32_t* r, uint32_t addr) {
    asm volatile("ldmatrix.sync.aligned.m8n8.x4.trans.shared.b16 {%0,%1,%2,%3}, [%4];"
        : "=r"(r[0]), "=r"(r[1]), "=r"(r[2]), "=r"(r[3]) : "r"(addr));
}

__device__ __forceinline__ void mma16816(float* c, const uint32_t* a, const uint32_t* b) {
    asm volatile("mma.sync.aligned.m16n8k16.row.col.f32.bf16.bf16.f32 "
        "{%0,%1,%2,%3}, {%4,%5,%6,%7}, {%8,%9}, {%0,%1,%2,%3};"
        : "+f"(c[0]), "+f"(c[1]), "+f"(c[2]), "+f"(c[3])
        : "r"(a[0]), "r"(a[1]), "r"(a[2]), "r"(a[3]), "r"(b[0]), "r"(b[1]));
}

__device__ __forceinline__ void wsplit(__nv_bfloat16* hi, __nv_bfloat16* lo,
                                       size_t idx, float v) {
    __nv_bfloat16 h = __float2bfloat16(v);
    hi[idx] = h;
    lo[idx] = __float2bfloat16(v - __bfloat162float(h));
}

__device__ __forceinline__ void split2(float a, float b, uint32_t& hi, uint32_t& lo) {
    __nv_bfloat16 ah = __float2bfloat16(a), bh = __float2bfloat16(b);
    float ar = a - __bfloat162float(ah), br = b - __bfloat162float(bh);
    __nv_bfloat162 h; h.x = ah; h.y = bh;
    __nv_bfloat162 l; l.x = __float2bfloat16(ar); l.y = __float2bfloat16(br);
    hi = *(uint32_t*)&h;
    lo = *(uint32_t*)&l;
}

// ---------------- combined input split kernel --------------------------------
// blocks: [0,2048) Xr | [2048,4096) Xi | [4096,7168) Wqr | [7168,10240) Wqi
// [10240,11264) Wor | [11264,12288) Woi | [12288,14336) Xs | [14336,17408) Wqs
// [17408,18432) Wos
__global__ void __launch_bounds__(256) split_all_kernel(
    const float* __restrict__ xr,  const float* __restrict__ xi,
    const float* __restrict__ wqr, const float* __restrict__ wqi,
    const float* __restrict__ wor, const float* __restrict__ woi)
{
    const int blk = blockIdx.x;
    const float *s1, *s2 = nullptr; __nv_bfloat16 *hi, *lo; int off;
    if      (blk <  2048) { s1 = xr;  hi = g_Xr_h;  lo = g_Xr_l;  off = blk; }
    else if (blk <  4096) { s1 = xi;  hi = g_Xi_h;  lo = g_Xi_l;  off = blk - 2048; }
    else if (blk <  7168) { s1 = wqr; hi = g_Wqr_h; lo = g_Wqr_l; off = blk - 4096; }
    else if (blk < 10240) { s1 = wqi; hi = g_Wqi_h; lo = g_Wqi_l; off = blk - 7168; }
    else if (blk < 11264) { s1 = wor; hi = g_Wor_h; lo = g_Wor_l; off = blk - 10240; }
    else if (blk < 12288) { s1 = woi; hi = g_Woi_h; lo = g_Woi_l; off = blk - 11264; }
    else if (blk < 14336) { s1 = xr;  s2 = xi;  hi = g_Xs_h;  lo = g_Xs_l;  off = blk - 12288; }
    else if (blk < 17408) { s1 = wqr; s2 = wqi; hi = g_Wqs_h; lo = g_Wqs_l; off = blk - 14336; }
    else                  { s1 = wor; s2 = woi; hi = g_Wos_h; lo = g_Wos_l; off = blk - 17408; }
    const int i = (off * 256 + threadIdx.x) * 4;
    float4 x = *(const float4*)(s1 + i);
    if (s2) {
        float4 y = *(const float4*)(s2 + i);
        x.x += y.x; x.y += y.y; x.z += y.z; x.w += y.w;
    }
    uint32_t h01, l01, h23, l23;
    split2(x.x, x.y, h01, l01);
    split2(x.z, x.w, h23, l23);
    *(uint2*)(hi + i) = make_uint2(h01, h23);
    *(uint2*)(lo + i) = make_uint2(l01, l23);
}

// ---------------- Karatsuba mma.sync complex GEMM core -----------------------
// Block 128(m) x 64(n), 256 threads, 8 warps as 8(m) x 1(n), warp tile 16x64.
// t1=ArBr, t2=AiBi, t3=(Ar+Ai)(Br+Bi); real=t1-t2, imag=t3-t1-t2.
// 6 variants each side (r_h, r_l, i_h, i_l, s_h, s_l). K-chunk 32, pitch 80B.
// Stage: A[v] at v*10240 (128x80B), B[v] at 61440 + v*5120 (64x80B).
#define STG 92160
#define GEMM_SMEM (2 * STG)
#define NCHUNK (DIMM / 32)

__device__ __forceinline__ void stage_load(uint32_t sA,
    const __nv_bfloat16* const* Av, const __nv_bfloat16* const* Bv,
    int m0, int e0, int k0, int tid)
{
    #pragma unroll
    for (int v = 0; v < 6; v++) {
        #pragma unroll
        for (int t = 0; t < 2; t++) {
            int idx = tid + t * 256;
            int r = idx >> 2, c = idx & 3;
            CP16(sA + v * 10240u + r * 80 + c * 16,
                 Av[v] + (size_t)(m0 + r) * DIMM + k0 + c * 8);
        }
        {
            int r = tid >> 2, c = tid & 3;
            CP16(sA + 61440u + v * 5120u + r * 80 + c * 16,
                 Bv[v] + (size_t)(e0 + r) * DIMM + k0 + c * 8);
        }
    }
}

__device__ __forceinline__ void gemm_compute(uint32_t ss, int lane, int wm,
    float t1[8][4], float t2[8][4], float t3[8][4])
{
    const uint32_t aRow = (uint32_t)(lane & 15);
    const uint32_t aSel = (uint32_t)(lane >> 4);
    const uint32_t nl   = (uint32_t)((lane & 7) + ((lane >> 4) << 3));
    const uint32_t ksel = (uint32_t)((lane >> 3) & 1);

    #pragma unroll
    for (int ks = 0; ks < 2; ks++) {
        uint32_t Af[6][4];   // Arh, Arl, Aih, Ail, Ash, Asl
        const uint32_t qa = ss + (wm * 16 + aRow) * 80u + aSel * 16u + ks * 32u;
        #pragma unroll
        for (int v = 0; v < 6; v++) ldm_x4(Af[v], qa + v * 10240u);

        #pragma unroll
        for (int h = 0; h < 4; h++) {
            uint32_t Bf[6][4];  // Brh, Brl, Bih, Bil, Bsh, Bsl
            const uint32_t ba = ss + 61440u
                + (h * 16 + nl) * 80u + ksel * 16u + ks * 32u;
            #pragma unroll
            for (int v = 0; v < 6; v++) ldm_x4(Bf[v], ba + v * 5120u);
            #pragma unroll
            for (int sub = 0; sub < 2; sub++) {
                const int nf = h * 2 + sub;
                const uint32_t* Brh = &Bf[0][sub * 2];
                const uint32_t* Brl = &Bf[1][sub * 2];
                const uint32_t* Bih = &Bf[2][sub * 2];
                const uint32_t* Bil = &Bf[3][sub * 2];
                const uint32_t* Bsh = &Bf[4][sub * 2];
                const uint32_t* Bsl = &Bf[5][sub * 2];
                // t1 = Ar*Br
                mma16816(t1[nf], Af[0], Brh);
                mma16816(t1[nf], Af[0], Brl);
                mma16816(t1[nf], Af[1], Brh);
                // t2 = Ai*Bi
                mma16816(t2[nf], Af[2], Bih);
                mma16816(t2[nf], Af[2], Bil);
                mma16816(t2[nf], Af[3], Bih);
                // t3 = As*Bs
                mma16816(t3[nf], Af[4], Bsh);
                mma16816(t3[nf], Af[4], Bsl);
                mma16816(t3[nf], Af[5], Bsh);
            }
        }
    }
}

// ---------------- qkv GEMM: fused bias + rotary + split-scatter --------------
__global__ void __launch_bounds__(256, 1) qkv_mma_kernel(
    const float* __restrict__ br, const float* __restrict__ bi,
    const float* __restrict__ fr, const float* __restrict__ fi)
{
    extern __shared__ char smrw[];
    const uint32_t sb = smem_u32(smrw);
    const int tid = threadIdx.x, lane = tid & 31, wm = tid >> 5;
    const int e0 = blockIdx.x * 64, m0 = blockIdx.y * 128;

    const __nv_bfloat16* Av[6] = {g_Xr_h, g_Xr_l, g_Xi_h, g_Xi_l, g_Xs_h, g_Xs_l};
    const __nv_bfloat16* Bv[6] = {g_Wqr_h, g_Wqr_l, g_Wqi_h, g_Wqi_l, g_Wqs_h, g_Wqs_l};

    float t1[8][4] = {}, t2[8][4] = {}, t3[8][4] = {};

    stage_load(sb, Av, Bv, m0, e0, 0, tid);
    CP_COMMIT();

    #pragma unroll 1
    for (int c = 0; c < NCHUNK; c++) {
        const int s = c & 1;
        if (c + 1 < NCHUNK) {
            stage_load(sb + (s ^ 1) * STG, Av, Bv, m0, e0, (c + 1) * 32, tid);
            CP_COMMIT();
            CP_WAIT(1);
        } else {
            CP_WAIT(0);
        }
        __syncthreads();
        gemm_compute(sb + s * STG, lane, wm, t1, t2, t3);
        __syncthreads();
    }

    #pragma unroll
    for (int nf = 0; nf < 8; nf++)
        #pragma unroll
        for (int rp = 0; rp < 2; rp++)
            #pragma unroll
            for (int cp = 0; cp < 2; cp++) {
                const int p = rp * 2 + cp;
                const int m = m0 + wm * 16 + (lane >> 2) + rp * 8;
                const int e = e0 + nf * 8 + (lane & 3) * 2 + cp;
                const float vr = t1[nf][p] - t2[nf][p] + br[e];
                const float vi = t3[nf][p] - t1[nf][p] - t2[nf][p] + bi[e];
                const int b = m >> 10;
                const int n = m & 1023;
                const int h = e / (HD * 3);
                const int rem = e % (HD * 3);
                const int d = rem / 3;
                const int which = rem % 3;
                const size_t idx = ((size_t)(b * HEADS + h) * Nn + n) * HD + d;
                if (which == 2) {
                    wsplit(g_Vrh, g_Vrl, idx, vr);
                    wsplit(g_Vih, g_Vil, idx, vi);
                } else {
                    const float frv = fr[n * HD + d];
                    const float fiv = fi[n * HD + d];
                    const float rr = vr * frv - vi * fiv;
                    const float ii = vr * fiv + vi * frv;
                    if (which == 0) {
                        wsplit(g_Qrh, g_Qrl, idx, rr);
                        wsplit(g_Qih, g_Qil, idx, ii);
                    } else {
                        wsplit(g_Krh, g_Krl, idx, rr);
                        wsplit(g_Kih, g_Kil, idx, ii);
                    }
                }
            }
}

// ---------------- output GEMM ------------------------------------------------
__global__ void __launch_bounds__(256, 1) out_mma_kernel(
    const float* __restrict__ br, const float* __restrict__ bi,
    float* __restrict__ out)
{
    extern __shared__ char smrw[];
    const uint32_t sb = smem_u32(smrw);
    const int tid = threadIdx.x, lane = tid & 31, wm = tid >> 5;
    const int e0 = blockIdx.x * 64, m0 = blockIdx.y * 128;

    const __nv_bfloat16* Av[6] = {g_Ar_h, g_Ar_l, g_Ai_h, g_Ai_l, g_As_h, g_As_l};
    const __nv_bfloat16* Bv[6] = {g_Wor_h, g_Wor_l, g_Woi_h, g_Woi_l, g_Wos_h, g_Wos_l};

    float t1[8][4] = {}, t2[8][4] = {}, t3[8][4] = {};

    stage_load(sb, Av, Bv, m0, e0, 0, tid);
    CP_COMMIT();

    #pragma unroll 1
    for (int c = 0; c < NCHUNK; c++) {
        const int s = c & 1;
        if (c + 1 < NCHUNK) {
            stage_load(sb + (s ^ 1) * STG, Av, Bv, m0, e0, (c + 1) * 32, tid);
            CP_COMMIT();
            CP_WAIT(1);
        } else {
            CP_WAIT(0);
        }
        __syncthreads();
        gemm_compute(sb + s * STG, lane, wm, t1, t2, t3);
        __syncthreads();
    }

    #pragma unroll
    for (int nf = 0; nf < 8; nf++)
        #pragma unroll
        for (int rp = 0; rp < 2; rp++)
            #pragma unroll
            for (int cp = 0; cp < 2; cp++) {
                const int p = rp * 2 + cp;
                const int m = m0 + wm * 16 + (lane >> 2) + rp * 8;
                const int e = e0 + nf * 8 + (lane & 3) * 2 + cp;
                out[(size_t)m * DIMM + e] = t1[nf][p] - t2[nf][p] + br[e];
                out[(size_t)Mtot * DIMM + (size_t)m * DIMM + e] =
                    t3[nf][p] - t1[nf][p] - t2[nf][p] + bi[e];
            }
}

// ---------------- tensor-core flash attention (unchanged) --------------------
#define PCH 144
#define VAR_Q  18432
#define VAR_KV 9216
#define SK_OFF 73728
#define SV_OFF 147456
#define STG_KV 36864
#define ATTN_SMEM 221184

__device__ __forceinline__ void load_kv(uint32_t sb,
    const __nv_bfloat16* const* Kv, const __nv_bfloat16* const* Vv,
    int k0, int s, int tid)
{
    #pragma unroll
    for (int v = 0; v < 4; v++)
        #pragma unroll
        for (int t = 0; t < 2; t++) {
            int i = tid + t * 256;
            int r = i >> 3, c = i & 7;
            CP16(sb + SK_OFF + s * STG_KV + v * VAR_KV + r * PCH + c * 16,
                 Kv[v] + (size_t)(k0 + r) * HD + c * 8);
            CP16(sb + SV_OFF + s * STG_KV + v * VAR_KV + r * PCH + c * 16,
                 Vv[v] + (size_t)(k0 + r) * HD + c * 8);
        }
}

__global__ void __launch_bounds__(256, 1) attn_mma_kernel()
{
    extern __shared__ char smrw[];
    const uint32_t sb = smem_u32(smrw);
    const int tid = threadIdx.x, lane = tid & 31, wid = tid >> 5;
    const int bh = blockIdx.y, q0 = blockIdx.x * 128;
    const size_t base = (size_t)bh * Nn * HD;

    const __nv_bfloat16* Qv[4] = {g_Qrh + base, g_Qrl + base, g_Qih + base, g_Qil + base};
    const __nv_bfloat16* Kv[4] = {g_Krh + base, g_Krl + base, g_Kih + base, g_Kil + base};
    const __nv_bfloat16* Vv[4] = {g_Vrh + base, g_Vrl + base, g_Vih + base, g_Vil + base};

    #pragma unroll
    for (int v = 0; v < 4; v++)
        #pragma unroll
        for (int t = 0; t < 4; t++) {
            int i = tid + t * 256;
            int r = i >> 3, c = i & 7;
            CP16(sb + v * VAR_Q + r * PCH + c * 16, Qv[v] + (size_t)(q0 + r) * HD + c * 8);
        }
    load_kv(sb, Kv, Vv, 0, 0, tid);
    CP_COMMIT();

    float oR[8][4] = {}, oI[8][4] = {};
    float m0 = -1e30f, m1 = -1e30f, l0 = 0.f, l1 = 0.f;
    const int r0 = wid * 16;

    #pragma unroll 1
    for (int kt = 0; kt < 16; kt++) {
        const int s = kt & 1;
        if (kt + 1 < 16) {
            load_kv(sb, Kv, Vv, (kt + 1) * 64, s ^ 1, tid);
            CP_COMMIT();
            CP_WAIT(1);
        } else {
            CP_WAIT(0);
        }
        __syncthreads();

        const uint32_t sK = sb + SK_OFF + s * STG_KV;
        const uint32_t sV = sb + SV_OFF + s * STG_KV;

        float sR[8][4] = {}, sI[8][4] = {};
        #pragma unroll
        for (int ks = 0; ks < 4; ks++) {
            uint32_t Qf[4][4];
            const uint32_t qa = sb + (r0 + (lane & 15)) * PCH + (lane >> 4) * 16 + ks * 32;
            #pragma unroll
            for (int v = 0; v < 4; v++) ldm_x4(Qf[v], qa + v * VAR_Q);
            uint32_t nQrh[4], nQrl[4];
            #pragma unroll
            for (int q = 0; q < 4; q++) {
                nQrh[q] = Qf[0][q] ^ 0x80008000u;
                nQrl[q] = Qf[1][q] ^ 0x80008000u;
            }
            #pragma unroll
            for (int np = 0; np < 4; np++) {
                uint32_t Kf[4][4];
                const uint32_t ka = sK + (np * 16 + (lane >> 4) * 8 + (lane & 7)) * PCH
                                    + ((lane >> 3) & 1) * 16 + ks * 32;
                #pragma unroll
                for (int v = 0; v < 4; v++) ldm_x4(Kf[v], ka + v * VAR_KV);
                #pragma unroll
                for (int sub = 0; sub < 2; sub++) {
                    const int nt = np * 2 + sub;
                    const uint32_t* Krh = &Kf[0][sub * 2];
                    const uint32_t* Krl = &Kf[1][sub * 2];
                    const uint32_t* Kih = &Kf[2][sub * 2];
                    const uint32_t* Kil = &Kf[3][sub * 2];
                    mma16816(sR[nt], Qf[0], Krh);
                    mma16816(sR[nt], Qf[0], Krl);
                    mma16816(sR[nt], Qf[1], Krh);
                    mma16816(sR[nt], Qf[2], Kih);
                    mma16816(sR[nt], Qf[2], Kil);
                    mma16816(sR[nt], Qf[3], Kih);
                    mma16816(sI[nt], Qf[2], Krh);
                    mma16816(sI[nt], Qf[2], Krl);
                    mma16816(sI[nt], Qf[3], Krh);
                    mma16816(sI[nt], nQrh,  Kih);
                    mma16816(sI[nt], nQrh,  Kil);
                    mma16816(sI[nt], nQrl,  Kih);
                }
            }
        }

        float vm0 = -1e30f, vm1 = -1e30f;
        #pragma unroll
        for (int nt = 0; nt < 8; nt++)
            #pragma unroll
            for (int p = 0; p < 4; p++) {
                const float v = 0.125f * sqrtf(sR[nt][p] * sR[nt][p] + sI[nt][p] * sI[nt][p]);
                sR[nt][p] = v;
                if (p < 2) vm0 = fmaxf(vm0, v); else vm1 = fmaxf(vm1, v);
            }
        vm0 = fmaxf(vm0, __shfl_xor_sync(0xffffffffu, vm0, 1));
        vm0 = fmaxf(vm0, __shfl_xor_sync(0xffffffffu, vm0, 2));
        vm1 = fmaxf(vm1, __shfl_xor_sync(0xffffffffu, vm1, 1));
        vm1 = fmaxf(vm1, __shfl_xor_sync(0xffffffffu, vm1, 2));
        const float mn0 = fmaxf(m0, vm0), mn1 = fmaxf(m1, vm1);
        const float a0 = __expf(m0 - mn0), a1 = __expf(m1 - mn1);
        m0 = mn0; m1 = mn1;
        #pragma unroll
        for (int nt = 0; nt < 8; nt++)
            #pragma unroll
            for (int p = 0; p < 4; p++) {
                const float al = (p < 2) ? a0 : a1;
                oR[nt][p] *= al;
                oI[nt][p] *= al;
            }
        float s0 = 0.f, s1 = 0.f;
        #pragma unroll
        for (int nt = 0; nt < 8; nt++)
            #pragma unroll
            for (int p = 0; p < 4; p++) {
                const float pv = __expf(sR[nt][p] - ((p < 2) ? mn0 : mn1));
                sR[nt][p] = pv;
                if (p < 2) s0 += pv; else s1 += pv;
            }
        s0 += __shfl_xor_sync(0xffffffffu, s0, 1);
        s0 += __shfl_xor_sync(0xffffffffu, s0, 2);
        s1 += __shfl_xor_sync(0xffffffffu, s1, 1);
        s1 += __shfl_xor_sync(0xffffffffu, s1, 2);
        l0 = l0 * a0 + s0;
        l1 = l1 * a1 + s1;

        uint32_t Ph[4][4], Pl[4][4];
        #pragma unroll
        for (int j = 0; j < 4; j++) {
            const int t0 = 2 * j, t1v = 2 * j + 1;
            split2(sR[t0][0], sR[t0][1], Ph[j][0], Pl[j][0]);
            split2(sR[t0][2], sR[t0][3], Ph[j][1], Pl[j][1]);
            split2(sR[t1v][0], sR[t1v][1], Ph[j][2], Pl[j][2]);
            split2(sR[t1v][2], sR[t1v][3], Ph[j][3], Pl[j][3]);
        }

        #pragma unroll
        for (int j = 0; j < 4; j++) {
            #pragma unroll
            for (int g = 0; g < 4; g++) {
                uint32_t Vf[4][4];
                const uint32_t va = sV + (j * 16 + ((lane >> 3) & 1) * 8 + (lane & 7)) * PCH
                                    + (lane >> 4) * 16 + g * 32;
                #pragma unroll
                for (int v = 0; v < 4; v++) ldm_x4_t(Vf[v], va + v * VAR_KV);
                #pragma unroll
                for (int sub = 0; sub < 2; sub++) {
                    const int nt = g * 2 + sub;
                    const uint32_t* Vrh = &Vf[0][sub * 2];
                    const uint32_t* Vrl = &Vf[1][sub * 2];
                    const uint32_t* Vih = &Vf[2][sub * 2];
                    const uint32_t* Vil = &Vf[3][sub * 2];
                    mma16816(oR[nt], Ph[j], Vrh);
                    mma16816(oR[nt], Pl[j], Vrh);
                    mma16816(oR[nt], Ph[j], Vrl);
                    mma16816(oI[nt], Ph[j], Vih);
                    mma16816(oI[nt], Pl[j], Vih);
                    mma16816(oI[nt], Ph[j], Vil);
                }
            }
        }
        __syncthreads();
    }

    const float inv0 = 1.0f / l0, inv1 = 1.0f / l1;
    const int b = bh / HEADS, h = bh % HEADS;
    #pragma unroll
    for (int nt = 0; nt < 8; nt++)
        #pragma unroll
        for (int p = 0; p < 4; p++) {
            const int n = q0 + r0 + (lane >> 2) + (p >> 1) * 8;
            const int d = nt * 8 + (lane & 3) * 2 + (p & 1);
            const float inv = (p < 2) ? inv0 : inv1;
            const size_t idx = ((size_t)(b * Nn + n)) * DIMM + h * HD + d;
            const float vr = oR[nt][p] * inv;
            const float vi = oI[nt][p] * inv;
            wsplit(g_Ar_h, g_Ar_l, idx, vr);
            wsplit(g_Ai_h, g_Ai_l, idx, vi);
            wsplit(g_As_h, g_As_l, idx, vr + vi);
        }
}

// ---------------- launch ------------------------------------------------------
extern "C" void kernel_launch(void* const* d_in, const int* in_sizes, int n_in,
                              void* d_out, int out_size)
{
    const float* xr  = (const float*)d_in[0];
    const float* xi  = (const float*)d_in[1];
    const float* fr  = (const float*)d_in[2];
    const float* fi  = (const float*)d_in[3];
    const float* wqr = (const float*)d_in[4];
    const float* wqi = (const float*)d_in[5];
    const float* bqr = (const float*)d_in[6];
    const float* bqi = (const float*)d_in[7];
    const float* wor = (const float*)d_in[8];
    const float* woi = (const float*)d_in[9];
    const float* bor = (const float*)d_in[10];
    const float* boi = (const float*)d_in[11];
    float* out = (float*)d_out;

    cudaFuncSetAttribute(qkv_mma_kernel,
                         cudaFuncAttributeMaxDynamicSharedMemorySize, GEMM_SMEM);
    cudaFuncSetAttribute(out_mma_kernel,
                         cudaFuncAttributeMaxDynamicSharedMemorySize, GEMM_SMEM);
    cudaFuncSetAttribute(attn_mma_kernel,
                         cudaFuncAttributeMaxDynamicSharedMemorySize, ATTN_SMEM);

    split_all_kernel<<<18432, 256>>>(xr, xi, wqr, wqi, wor, woi);
    qkv_mma_kernel<<<dim3(E3 / 64, Mtot / 128), 256, GEMM_SMEM>>>(bqr, bqi, fr, fi);
    attn_mma_kernel<<<dim3(Nn / 128, Bb * HEADS), 256, ATTN_SMEM>>>();
    out_mma_kernel<<<dim3(DIMM / 64, Mtot / 128), 256, GEMM_SMEM>>>(bor, boi, out);
}

// round 8
// speedup vs baseline: 1.3094x; 1.3094x over previous
#include <cuda_runtime.h>
#include <cuda_bf16.h>
#include <stdint.h>
#include <math.h>

#define Bb    2
#define Nn    1024
#define DIMM  1024
#define HEADS 16
#define HD    64
#define Mtot  (Bb * Nn)      // 2048
#define E3    (3 * DIMM)     // 3072

// ---------------- bf16 hi/lo split scratch -----------------------------------
__device__ __nv_bfloat16 g_Xr_h[Mtot * DIMM], g_Xr_l[Mtot * DIMM];
__device__ __nv_bfloat16 g_Xi_h[Mtot * DIMM], g_Xi_l[Mtot * DIMM];
__device__ __nv_bfloat16 g_Wqr_h[E3 * DIMM],  g_Wqr_l[E3 * DIMM];
__device__ __nv_bfloat16 g_Wqi_h[E3 * DIMM],  g_Wqi_l[E3 * DIMM];
__device__ __nv_bfloat16 g_Wor_h[DIMM * DIMM], g_Wor_l[DIMM * DIMM];
__device__ __nv_bfloat16 g_Woi_h[DIMM * DIMM], g_Woi_l[DIMM * DIMM];
__device__ __nv_bfloat16 g_Ar_h[Mtot * DIMM], g_Ar_l[Mtot * DIMM];
__device__ __nv_bfloat16 g_Ai_h[Mtot * DIMM], g_Ai_l[Mtot * DIMM];

// Q/K/V bf16 hi/lo, layout [b*H + h][d][n]  (n innermost!)
#define QKV_SZ (Bb * HEADS * Nn * HD)
__device__ __nv_bfloat16 g_Qrh[QKV_SZ], g_Qrl[QKV_SZ], g_Qih[QKV_SZ], g_Qil[QKV_SZ];
__device__ __nv_bfloat16 g_Krh[QKV_SZ], g_Krl[QKV_SZ], g_Kih[QKV_SZ], g_Kil[QKV_SZ];
__device__ __nv_bfloat16 g_Vrh[QKV_SZ], g_Vrl[QKV_SZ], g_Vih[QKV_SZ], g_Vil[QKV_SZ];

// ---------------- helpers ----------------------------------------------------
__device__ __forceinline__ uint32_t smem_u32(const void* p) {
    uint32_t a;
    asm("{ .reg .u64 t; cvta.to.shared.u64 t, %1; cvt.u32.u64 %0, t; }"
        : "=r"(a) : "l"(p));
    return a;
}

#define CP16(dst, src) \
    asm volatile("cp.async.cg.shared.global [%0], [%1], 16;" \
                 :: "r"((uint32_t)(dst)), "l"(src) : "memory")
#define CP_COMMIT() asm volatile("cp.async.commit_group;" ::: "memory")
#define CP_WAIT(n)  asm volatile("cp.async.wait_group %0;" :: "n"(n) : "memory")

__device__ __forceinline__ void ldm_x4(uint32_t* r, uint32_t addr) {
    asm volatile("ldmatrix.sync.aligned.m8n8.x4.shared.b16 {%0,%1,%2,%3}, [%4];"
        : "=r"(r[0]), "=r"(r[1]), "=r"(r[2]), "=r"(r[3]) : "r"(addr));
}

__device__ __forceinline__ void ldm_x4_t(uint32_t* r, uint32_t addr) {
    asm volatile("ldmatrix.sync.aligned.m8n8.x4.trans.shared.b16 {%0,%1,%2,%3}, [%4];"
        : "=r"(r[0]), "=r"(r[1]), "=r"(r[2]), "=r"(r[3]) : "r"(addr));
}

__device__ __forceinline__ void mma16816(float* c, const uint32_t* a, const uint32_t* b) {
    asm volatile("mma.sync.aligned.m16n8k16.row.col.f32.bf16.bf16.f32 "
        "{%0,%1,%2,%3}, {%4,%5,%6,%7}, {%8,%9}, {%0,%1,%2,%3};"
        : "+f"(c[0]), "+f"(c[1]), "+f"(c[2]), "+f"(c[3])
        : "r"(a[0]), "r"(a[1]), "r"(a[2]), "r"(a[3]), "r"(b[0]), "r"(b[1]));
}

__device__ __forceinline__ void split2(float a, float b, uint32_t& hi, uint32_t& lo) {
    __nv_bfloat16 ah = __float2bfloat16(a), bh = __float2bfloat16(b);
    float ar = a - __bfloat162float(ah), br = b - __bfloat162float(bh);
    __nv_bfloat162 h; h.x = ah; h.y = bh;
    __nv_bfloat162 l; l.x = __float2bfloat16(ar); l.y = __float2bfloat16(br);
    hi = *(uint32_t*)&h;
    lo = *(uint32_t*)&l;
}

// ---------------- combined input split kernel --------------------------------
__global__ void __launch_bounds__(256) split_all_kernel(
    const float* __restrict__ xr,  const float* __restrict__ xi,
    const float* __restrict__ wqr, const float* __restrict__ wqi,
    const float* __restrict__ wor, const float* __restrict__ woi)
{
    const int blk = blockIdx.x;
    const float* src; __nv_bfloat16 *hi, *lo; int off;
    if      (blk <  2048) { src = xr;  hi = g_Xr_h;  lo = g_Xr_l;  off = blk; }
    else if (blk <  4096) { src = xi;  hi = g_Xi_h;  lo = g_Xi_l;  off = blk - 2048; }
    else if (blk <  7168) { src = wqr; hi = g_Wqr_h; lo = g_Wqr_l; off = blk - 4096; }
    else if (blk < 10240) { src = wqi; hi = g_Wqi_h; lo = g_Wqi_l; off = blk - 7168; }
    else if (blk < 11264) { src = wor; hi = g_Wor_h; lo = g_Wor_l; off = blk - 10240; }
    else                  { src = woi; hi = g_Woi_h; lo = g_Woi_l; off = blk - 11264; }
    const int i = (off * 256 + threadIdx.x) * 4;
    float4 x = *(const float4*)(src + i);
    uint32_t h01, l01, h23, l23;
    split2(x.x, x.y, h01, l01);
    split2(x.z, x.w, h23, l23);
    *(uint2*)(hi + i) = make_uint2(h01, h23);
    *(uint2*)(lo + i) = make_uint2(l01, l23);
}

// ---------------- mma.sync complex GEMM core (R5 config) ---------------------
// Block 128x128, 256 threads, 8 warps as 4(m) x 2(n), warp tile 32x64.
#define STG 81920
#define GEMM_SMEM (2 * STG)
#define NCHUNK (DIMM / 32)

__device__ __forceinline__ void stage_load(uint32_t sA,
    const __nv_bfloat16* const* Av, const __nv_bfloat16* const* Bv,
    int m0, int e0, int k0, int tid)
{
    #pragma unroll
    for (int v = 0; v < 4; v++) {
        const __nv_bfloat16* srcA = Av[v] + (size_t)m0 * DIMM + k0;
        uint32_t dstA = sA + v * 10240u;
        #pragma unroll
        for (int t = 0; t < 2; t++) {
            int idx = tid + t * 256;
            int r = idx >> 2, c = idx & 3;
            CP16(dstA + r * 80 + c * 16, srcA + (size_t)r * DIMM + c * 8);
        }
        const __nv_bfloat16* srcB = Bv[v] + (size_t)e0 * DIMM + k0;
        uint32_t dstB = sA + 40960u + v * 10240u;
        #pragma unroll
        for (int t = 0; t < 2; t++) {
            int idx = tid + t * 256;
            int r = idx >> 2, c = idx & 3;
            CP16(dstB + r * 80 + c * 16, srcB + (size_t)r * DIMM + c * 8);
        }
    }
}

__device__ __forceinline__ void gemm_compute(uint32_t ss, int lane, int wm, int wn,
    float accR[2][8][4], float accI[2][8][4])
{
    const uint32_t aRow = (uint32_t)(lane & 15);
    const uint32_t aSel = (uint32_t)(lane >> 4);
    const uint32_t nl   = (uint32_t)((lane & 7) + ((lane >> 4) << 3));
    const uint32_t ksel = (uint32_t)((lane >> 3) & 1);

    #pragma unroll
    for (int ks = 0; ks < 2; ks++) {
        uint32_t Af[4][2][4];
        #pragma unroll
        for (int v = 0; v < 4; v++)
            #pragma unroll
            for (int mf = 0; mf < 2; mf++) {
                uint32_t addr = ss + v * 10240u
                    + (wm * 32 + mf * 16 + aRow) * 80u + aSel * 16u + ks * 32u;
                ldm_x4(Af[v][mf], addr);
            }
        uint32_t nAih[2][4], nAil[2][4];
        #pragma unroll
        for (int mf = 0; mf < 2; mf++)
            #pragma unroll
            for (int q = 0; q < 4; q++) {
                nAih[mf][q] = Af[2][mf][q] ^ 0x80008000u;
                nAil[mf][q] = Af[3][mf][q] ^ 0x80008000u;
            }
        #pragma unroll
        for (int h = 0; h < 4; h++) {
            uint32_t Bf[4][4];
            #pragma unroll
            for (int v = 0; v < 4; v++) {
                uint32_t addr = ss + 40960u + v * 10240u
                    + (wn * 64 + h * 16 + nl) * 80u + ksel * 16u + ks * 32u;
                ldm_x4(Bf[v], addr);
            }
            #pragma unroll
            for (int mf = 0; mf < 2; mf++)
                #pragma unroll
                for (int sub = 0; sub < 2; sub++) {
                    const int nf = h * 2 + sub;
                    const uint32_t* Brh = &Bf[0][sub * 2];
                    const uint32_t* Brl = &Bf[1][sub * 2];
                    const uint32_t* Bih = &Bf[2][sub * 2];
                    const uint32_t* Bil = &Bf[3][sub * 2];
                    float* cr = accR[mf][nf];
                    float* ci = accI[mf][nf];
                    mma16816(cr, Af[0][mf], Brh);
                    mma16816(cr, Af[0][mf], Brl);
                    mma16816(cr, Af[1][mf], Brh);
                    mma16816(cr, nAih[mf],  Bih);
                    mma16816(cr, nAih[mf],  Bil);
                    mma16816(cr, nAil[mf],  Bih);
                    mma16816(ci, Af[0][mf], Bih);
                    mma16816(ci, Af[0][mf], Bil);
                    mma16816(ci, Af[1][mf], Bih);
                    mma16816(ci, Af[2][mf], Brh);
                    mma16816(ci, Af[2][mf], Brl);
                    mma16816(ci, Af[3][mf], Brh);
                }
        }
    }
}

// ---------------- qkv GEMM: smem-staged epilogue, [bh][d][n] writes ----------
__global__ void __launch_bounds__(256, 1) qkv_mma_kernel(
    const float* __restrict__ br, const float* __restrict__ bi,
    const float* __restrict__ fr, const float* __restrict__ fi)
{
    extern __shared__ char smrw[];
    const uint32_t sb = smem_u32(smrw);
    const int tid = threadIdx.x, lane = tid & 31, wid = tid >> 5;
    const int wm = wid >> 1, wn = wid & 1;
    const int e0 = blockIdx.x * 128, m0 = blockIdx.y * 128;

    const __nv_bfloat16* Av[4] = {g_Xr_h, g_Xr_l, g_Xi_h, g_Xi_l};
    const __nv_bfloat16* Bv[4] = {g_Wqr_h, g_Wqr_l, g_Wqi_h, g_Wqi_l};

    float accR[2][8][4] = {}, accI[2][8][4] = {};

    stage_load(sb, Av, Bv, m0, e0, 0, tid);
    CP_COMMIT();

    #pragma unroll 1
    for (int c = 0; c < NCHUNK; c++) {
        const int s = c & 1;
        if (c + 1 < NCHUNK) {
            stage_load(sb + (s ^ 1) * STG, Av, Bv, m0, e0, (c + 1) * 32, tid);
            CP_COMMIT();
            CP_WAIT(1);
        } else {
            CP_WAIT(0);
        }
        __syncthreads();
        gemm_compute(sb + s * STG, lane, wm, wn, accR, accI);
        __syncthreads();
    }

    // ---- stage accumulators to smem as [e 128][m pitch 132] fp32 ----
    float* smr = (float*)smrw;
    float* smi = smr + 128 * 132;
    #pragma unroll
    for (int mf = 0; mf < 2; mf++)
        #pragma unroll
        for (int nf = 0; nf < 8; nf++)
            #pragma unroll
            for (int rp = 0; rp < 2; rp++)
                #pragma unroll
                for (int cp = 0; cp < 2; cp++) {
                    const int el = wn * 64 + nf * 8 + (lane & 3) * 2 + cp;
                    const int ml = wm * 32 + mf * 16 + (lane >> 2) + rp * 8;
                    smr[el * 132 + ml] = accR[mf][nf][rp * 2 + cp];
                    smi[el * 132 + ml] = accI[mf][nf][rp * 2 + cp];
                }
    __syncthreads();

    // ---- each thread: one e-column half, packed uint2 n-run stores ----
    const int el = tid >> 1, half = tid & 1;
    const int e = e0 + el;
    const int h = e / 192, rem = e % 192;
    const int d = rem / 3, which = rem % 3;
    const float bre = br[e], bie = bi[e];
    const int b = m0 >> 10, n0 = (m0 & 1023) + half * 64;
    const int bh = b * HEADS + h;
    __nv_bfloat16 *dRh, *dRl, *dIh, *dIl;
    if (which == 0)      { dRh = g_Qrh; dRl = g_Qrl; dIh = g_Qih; dIl = g_Qil; }
    else if (which == 1) { dRh = g_Krh; dRl = g_Krl; dIh = g_Kih; dIl = g_Kil; }
    else                 { dRh = g_Vrh; dRl = g_Vrl; dIh = g_Vih; dIl = g_Vil; }
    const size_t dbase = (size_t)(bh * HD + d) * Nn + n0;
    const float* smr_e = smr + el * 132 + half * 64;
    const float* smi_e = smi + el * 132 + half * 64;

    #pragma unroll 1
    for (int mc = 0; mc < 16; mc++) {
        float4 srv = *(const float4*)(smr_e + mc * 4);
        float4 siv = *(const float4*)(smi_e + mc * 4);
        float vr[4] = {srv.x + bre, srv.y + bre, srv.z + bre, srv.w + bre};
        float vi[4] = {siv.x + bie, siv.y + bie, siv.z + bie, siv.w + bie};
        if (which < 2) {
            #pragma unroll
            for (int j = 0; j < 4; j++) {
                const int n = n0 + mc * 4 + j;
                const float frv = fr[n * HD + d], fiv = fi[n * HD + d];
                const float rr = vr[j] * frv - vi[j] * fiv;
                vi[j] = vr[j] * fiv + vi[j] * frv;
                vr[j] = rr;
            }
        }
        uint32_t h01, l01, h23, l23;
        split2(vr[0], vr[1], h01, l01);
        split2(vr[2], vr[3], h23, l23);
        *(uint2*)(dRh + dbase + mc * 4) = make_uint2(h01, h23);
        *(uint2*)(dRl + dbase + mc * 4) = make_uint2(l01, l23);
        split2(vi[0], vi[1], h01, l01);
        split2(vi[2], vi[3], h23, l23);
        *(uint2*)(dIh + dbase + mc * 4) = make_uint2(h01, h23);
        *(uint2*)(dIl + dbase + mc * 4) = make_uint2(l01, l23);
    }
}

// ---------------- output GEMM (float2-packed epilogue) -----------------------
__global__ void __launch_bounds__(256, 1) out_mma_kernel(
    const float* __restrict__ br, const float* __restrict__ bi,
    float* __restrict__ out)
{
    extern __shared__ char smrw[];
    const uint32_t sb = smem_u32(smrw);
    const int tid = threadIdx.x, lane = tid & 31, wid = tid >> 5;
    const int wm = wid >> 1, wn = wid & 1;
    const int e0 = blockIdx.x * 128, m0 = blockIdx.y * 128;

    const __nv_bfloat16* Av[4] = {g_Ar_h, g_Ar_l, g_Ai_h, g_Ai_l};
    const __nv_bfloat16* Bv[4] = {g_Wor_h, g_Wor_l, g_Woi_h, g_Woi_l};

    float accR[2][8][4] = {}, accI[2][8][4] = {};

    stage_load(sb, Av, Bv, m0, e0, 0, tid);
    CP_COMMIT();

    #pragma unroll 1
    for (int c = 0; c < NCHUNK; c++) {
        const int s = c & 1;
        if (c + 1 < NCHUNK) {
            stage_load(sb + (s ^ 1) * STG, Av, Bv, m0, e0, (c + 1) * 32, tid);
            CP_COMMIT();
            CP_WAIT(1);
        } else {
            CP_WAIT(0);
        }
        __syncthreads();
        gemm_compute(sb + s * STG, lane, wm, wn, accR, accI);
        __syncthreads();
    }

    #pragma unroll
    for (int mf = 0; mf < 2; mf++)
        #pragma unroll
        for (int nf = 0; nf < 8; nf++)
            #pragma unroll
            for (int rp = 0; rp < 2; rp++) {
                const int m = m0 + wm * 32 + mf * 16 + (lane >> 2) + rp * 8;
                const int e = e0 + wn * 64 + nf * 8 + (lane & 3) * 2;
                float2 vr = make_float2(accR[mf][nf][rp * 2] + br[e],
                                        accR[mf][nf][rp * 2 + 1] + br[e + 1]);
                float2 vi = make_float2(accI[mf][nf][rp * 2] + bi[e],
                                        accI[mf][nf][rp * 2 + 1] + bi[e + 1]);
                *(float2*)&out[(size_t)m * DIMM + e] = vr;
                *(float2*)&out[(size_t)Mtot * DIMM + (size_t)m * DIMM + e] = vi;
            }
}

// ---------------- tensor-core flash attention ([bh][d][n] inputs) ------------
#define PCHQ 272
#define VQ   17408            // 64 * 272
#define PCHK 144
#define VKV  9216             // 64 * 144
#define SK_OFF (4 * VQ)                   // 69632
#define STG_KV (4 * VKV)                  // 36864
#define SV_OFF (SK_OFF + 2 * STG_KV)      // 143360
#define ATTN_SMEM (SV_OFF + 2 * STG_KV)   // 217088

__device__ __forceinline__ void load_kv(uint32_t sb,
    const __nv_bfloat16* const* Kv, const __nv_bfloat16* const* Vv,
    int k0, int s, int tid)
{
    #pragma unroll
    for (int v = 0; v < 4; v++)
        #pragma unroll
        for (int t = 0; t < 2; t++) {
            int i = tid + t * 256;
            int r = i >> 3, c = i & 7;   // r = d row, c = key chunk
            CP16(sb + SK_OFF + s * STG_KV + v * VKV + r * PCHK + c * 16,
                 Kv[v] + (size_t)r * Nn + k0 + c * 8);
            CP16(sb + SV_OFF + s * STG_KV + v * VKV + r * PCHK + c * 16,
                 Vv[v] + (size_t)r * Nn + k0 + c * 8);
        }
}

__global__ void __launch_bounds__(256, 1) attn_mma_kernel()
{
    extern __shared__ char smrw[];
    const uint32_t sb = smem_u32(smrw);
    const int tid = threadIdx.x, lane = tid & 31, wid = tid >> 5;
    const int bh = blockIdx.y, q0 = blockIdx.x * 128;
    const size_t base = (size_t)bh * Nn * HD;

    const __nv_bfloat16* Qv[4] = {g_Qrh + base, g_Qrl + base, g_Qih + base, g_Qil + base};
    const __nv_bfloat16* Kv[4] = {g_Krh + base, g_Krl + base, g_Kih + base, g_Kil + base};
    const __nv_bfloat16* Vv[4] = {g_Vrh + base, g_Vrl + base, g_Vih + base, g_Vil + base};

    // Q tile: 64 d rows x 128 n cols
    #pragma unroll
    for (int v = 0; v < 4; v++)
        #pragma unroll
        for (int t = 0; t < 4; t++) {
            int i = tid + t * 256;
            int r = i >> 4, c = i & 15;
            CP16(sb + v * VQ + r * PCHQ + c * 16, Qv[v] + (size_t)r * Nn + q0 + c * 8);
        }
    load_kv(sb, Kv, Vv, 0, 0, tid);
    CP_COMMIT();

    float oR[8][4] = {}, oI[8][4] = {};
    float m0 = -1e30f, m1 = -1e30f, l0 = 0.f, l1 = 0.f;
    const int r0 = wid * 16;

    #pragma unroll 1
    for (int kt = 0; kt < 16; kt++) {
        const int s = kt & 1;
        if (kt + 1 < 16) {
            load_kv(sb, Kv, Vv, (kt + 1) * 64, s ^ 1, tid);
            CP_COMMIT();
            CP_WAIT(1);
        } else {
            CP_WAIT(0);
        }
        __syncthreads();

        const uint32_t sK = sb + SK_OFF + s * STG_KV;
        const uint32_t sV = sb + SV_OFF + s * STG_KV;

        // ---- S = Q . conj(K) ----
        float sR[8][4] = {}, sI[8][4] = {};
        #pragma unroll
        for (int ks = 0; ks < 4; ks++) {
            uint32_t Qf[4][4];
            const uint32_t qa = sb
                + (ks * 16 + (lane & 7) + ((lane >> 4) & 1) * 8) * PCHQ
                + (r0 + ((lane >> 3) & 1) * 8) * 2;
            #pragma unroll
            for (int v = 0; v < 4; v++) ldm_x4_t(Qf[v], qa + v * VQ);
            uint32_t nQrh[4], nQrl[4];
            #pragma unroll
            for (int q = 0; q < 4; q++) {
                nQrh[q] = Qf[0][q] ^ 0x80008000u;
                nQrl[q] = Qf[1][q] ^ 0x80008000u;
            }
            #pragma unroll
            for (int np = 0; np < 4; np++) {
                uint32_t Kf[4][4];
                const uint32_t ka = sK
                    + (ks * 16 + (lane & 7) + ((lane >> 3) & 1) * 8) * PCHK
                    + (np * 16 + ((lane >> 4) & 1) * 8) * 2;
                #pragma unroll
                for (int v = 0; v < 4; v++) ldm_x4_t(Kf[v], ka + v * VKV);
                #pragma unroll
                for (int sub = 0; sub < 2; sub++) {
                    const int nt = np * 2 + sub;
                    const uint32_t* Krh = &Kf[0][sub * 2];
                    const uint32_t* Krl = &Kf[1][sub * 2];
                    const uint32_t* Kih = &Kf[2][sub * 2];
                    const uint32_t* Kil = &Kf[3][sub * 2];
                    mma16816(sR[nt], Qf[0], Krh);
                    mma16816(sR[nt], Qf[0], Krl);
                    mma16816(sR[nt], Qf[1], Krh);
                    mma16816(sR[nt], Qf[2], Kih);
                    mma16816(sR[nt], Qf[2], Kil);
                    mma16816(sR[nt], Qf[3], Kih);
                    mma16816(sI[nt], Qf[2], Krh);
                    mma16816(sI[nt], Qf[2], Krl);
                    mma16816(sI[nt], Qf[3], Krh);
                    mma16816(sI[nt], nQrh,  Kih);
                    mma16816(sI[nt], nQrh,  Kil);
                    mma16816(sI[nt], nQrl,  Kih);
                }
            }
        }

        // ---- online softmax on scaled |S| ----
        float vm0 = -1e30f, vm1 = -1e30f;
        #pragma unroll
        for (int nt = 0; nt < 8; nt++)
            #pragma unroll
            for (int p = 0; p < 4; p++) {
                const float v = 0.125f * sqrtf(sR[nt][p] * sR[nt][p] + sI[nt][p] * sI[nt][p]);
                sR[nt][p] = v;
                if (p < 2) vm0 = fmaxf(vm0, v); else vm1 = fmaxf(vm1, v);
            }
        vm0 = fmaxf(vm0, __shfl_xor_sync(0xffffffffu, vm0, 1));
        vm0 = fmaxf(vm0, __shfl_xor_sync(0xffffffffu, vm0, 2));
        vm1 = fmaxf(vm1, __shfl_xor_sync(0xffffffffu, vm1, 1));
        vm1 = fmaxf(vm1, __shfl_xor_sync(0xffffffffu, vm1, 2));
        const float mn0 = fmaxf(m0, vm0), mn1 = fmaxf(m1, vm1);
        const float a0 = __expf(m0 - mn0), a1 = __expf(m1 - mn1);
        m0 = mn0; m1 = mn1;
        #pragma unroll
        for (int nt = 0; nt < 8; nt++)
            #pragma unroll
            for (int p = 0; p < 4; p++) {
                const float al = (p < 2) ? a0 : a1;
                oR[nt][p] *= al;
                oI[nt][p] *= al;
            }
        float s0 = 0.f, s1 = 0.f;
        #pragma unroll
        for (int nt = 0; nt < 8; nt++)
            #pragma unroll
            for (int p = 0; p < 4; p++) {
                const float pv = __expf(sR[nt][p] - ((p < 2) ? mn0 : mn1));
                sR[nt][p] = pv;
                if (p < 2) s0 += pv; else s1 += pv;
            }
        s0 += __shfl_xor_sync(0xffffffffu, s0, 1);
        s0 += __shfl_xor_sync(0xffffffffu, s0, 2);
        s1 += __shfl_xor_sync(0xffffffffu, s1, 1);
        s1 += __shfl_xor_sync(0xffffffffu, s1, 2);
        l0 = l0 * a0 + s0;
        l1 = l1 * a1 + s1;

        // ---- pack P into A fragments ----
        uint32_t Ph[4][4], Pl[4][4];
        #pragma unroll
        for (int j = 0; j < 4; j++) {
            const int t0 = 2 * j, t1 = 2 * j + 1;
            split2(sR[t0][0], sR[t0][1], Ph[j][0], Pl[j][0]);
            split2(sR[t0][2], sR[t0][3], Ph[j][1], Pl[j][1]);
            split2(sR[t1][0], sR[t1][1], Ph[j][2], Pl[j][2]);
            split2(sR[t1][2], sR[t1][3], Ph[j][3], Pl[j][3]);
        }

        // ---- O += P @ V (non-trans on [d][key]) ----
        #pragma unroll
        for (int j = 0; j < 4; j++) {
            #pragma unroll
            for (int g = 0; g < 4; g++) {
                uint32_t Vf[4][4];
                const uint32_t va = sV
                    + (g * 16 + (lane & 7) + ((lane >> 4) & 1) * 8) * PCHK
                    + j * 32 + ((lane >> 3) & 1) * 16;
                #pragma unroll
                for (int v = 0; v < 4; v++) ldm_x4(Vf[v], va + v * VKV);
                #pragma unroll
                for (int sub = 0; sub < 2; sub++) {
                    const int nt = g * 2 + sub;
                    const uint32_t* Vrh = &Vf[0][sub * 2];
                    const uint32_t* Vrl = &Vf[1][sub * 2];
                    const uint32_t* Vih = &Vf[2][sub * 2];
                    const uint32_t* Vil = &Vf[3][sub * 2];
                    mma16816(oR[nt], Ph[j], Vrh);
                    mma16816(oR[nt], Pl[j], Vrh);
                    mma16816(oR[nt], Ph[j], Vrl);
                    mma16816(oI[nt], Ph[j], Vih);
                    mma16816(oI[nt], Pl[j], Vih);
                    mma16816(oI[nt], Ph[j], Vil);
                }
            }
        }
        __syncthreads();
    }

    // ---- normalize + packed pair writes to [b][n][h*64+d] ----
    const float inv0 = 1.0f / l0, inv1 = 1.0f / l1;
    const int b = bh / HEADS, h = bh % HEADS;
    #pragma unroll
    for (int nt = 0; nt < 8; nt++)
        #pragma unroll
        for (int rp = 0; rp < 2; rp++) {
            const int n = q0 + r0 + (lane >> 2) + rp * 8;
            const int d0 = nt * 8 + (lane & 3) * 2;
            const float inv = (rp == 0) ? inv0 : inv1;
            const size_t idx = ((size_t)(b * Nn + n)) * DIMM + h * HD + d0;
            uint32_t hh, ll;
            split2(oR[nt][rp * 2] * inv, oR[nt][rp * 2 + 1] * inv, hh, ll);
            *(uint32_t*)(g_Ar_h + idx) = hh;
            *(uint32_t*)(g_Ar_l + idx) = ll;
            split2(oI[nt][rp * 2] * inv, oI[nt][rp * 2 + 1] * inv, hh, ll);
            *(uint32_t*)(g_Ai_h + idx) = hh;
            *(uint32_t*)(g_Ai_l + idx) = ll;
        }
}

// ---------------- launch ------------------------------------------------------
extern "C" void kernel_launch(void* const* d_in, const int* in_sizes, int n_in,
                              void* d_out, int out_size)
{
    const float* xr  = (const float*)d_in[0];
    const float* xi  = (const float*)d_in[1];
    const float* fr  = (const float*)d_in[2];
    const float* fi  = (const float*)d_in[3];
    const float* wqr = (const float*)d_in[4];
    const float* wqi = (const float*)d_in[5];
    const float* bqr = (const float*)d_in[6];
    const float* bqi = (const float*)d_in[7];
    const float* wor = (const float*)d_in[8];
    const float* woi = (const float*)d_in[9];
    const float* bor = (const float*)d_in[10];
    const float* boi = (const float*)d_in[11];
    float* out = (float*)d_out;

    cudaFuncSetAttribute(qkv_mma_kernel,
                         cudaFuncAttributeMaxDynamicSharedMemorySize, GEMM_SMEM);
    cudaFuncSetAttribute(out_mma_kernel,
                         cudaFuncAttributeMaxDynamicSharedMemorySize, GEMM_SMEM);
    cudaFuncSetAttribute(attn_mma_kernel,
                         cudaFuncAttributeMaxDynamicSharedMemorySize, ATTN_SMEM);

    split_all_kernel<<<12288, 256>>>(xr, xi, wqr, wqi, wor, woi);
    qkv_mma_kernel<<<dim3(E3 / 128, Mtot / 128), 256, GEMM_SMEM>>>(bqr, bqi, fr, fi);
    attn_mma_kernel<<<dim3(Nn / 128, Bb * HEADS), 256, ATTN_SMEM>>>();
    out_mma_kernel<<<dim3(DIMM / 128, Mtot / 128), 256, GEMM_SMEM>>>(bor, boi, out);
}